// round 8
// baseline (speedup 1.0000x reference)
#include <cuda_runtime.h>
#include <cstdint>

// out[b, s, d] = x[b, s, d] - sum_d' x[b, s, d']
// x: (8, 8192, 512) fp32, 65536 rows of 2048 B.
// R6: two rows per warp, all loads front-batched (4 x 256-bit per lane =
// 128 B/lane in flight) to raise per-warp MLP; two independent shuffle
// reduction chains interleave in the issue slots. Default cache policy
// (R2-R5 showed all L2 hint variants are neutral-or-worse).

static constexpr int D = 512;

struct V8 { uint32_t r[8]; };

__device__ __forceinline__ V8 ldg256(const void* p) {
    V8 v;
    asm volatile(
        "ld.global.nc.v8.b32 {%0,%1,%2,%3,%4,%5,%6,%7}, [%8];"
        : "=r"(v.r[0]), "=r"(v.r[1]), "=r"(v.r[2]), "=r"(v.r[3]),
          "=r"(v.r[4]), "=r"(v.r[5]), "=r"(v.r[6]), "=r"(v.r[7])
        : "l"(p));
    return v;
}

__device__ __forceinline__ void stg256(void* p, const V8& v) {
    asm volatile(
        "st.global.v8.b32 [%0], {%1,%2,%3,%4,%5,%6,%7,%8};"
        :: "l"(p),
           "r"(v.r[0]), "r"(v.r[1]), "r"(v.r[2]), "r"(v.r[3]),
           "r"(v.r[4]), "r"(v.r[5]), "r"(v.r[6]), "r"(v.r[7])
        : "memory");
}

__device__ __forceinline__ float v8_sum2(const V8& a, const V8& b) {
    float s = 0.0f;
#pragma unroll
    for (int i = 0; i < 8; i++)
        s += __uint_as_float(a.r[i]) + __uint_as_float(b.r[i]);
    return s;
}

__device__ __forceinline__ void v8_sub(V8& a, float s) {
#pragma unroll
    for (int i = 0; i < 8; i++)
        a.r[i] = __float_as_uint(__uint_as_float(a.r[i]) - s);
}

// One warp per PAIR of rows.
__global__ void __launch_bounds__(256)
row_center_kernel(const float* __restrict__ x, float* __restrict__ out,
                  int n_pairs) {
    const int pair = (blockIdx.x * blockDim.x + threadIdx.x) >> 5;
    const int lane = threadIdx.x & 31;
    if (pair >= n_pairs) return;

    const char* rowA = (const char*)(x + (size_t)(2 * pair) * D);
    const char* rowB = rowA + 2048;
    char* orowA = (char*)(out + (size_t)(2 * pair) * D);
    char* orowB = orowA + 2048;

    // Front-batch all 4 loads: 128 B/lane outstanding.
    V8 a0 = ldg256(rowA + 32 * lane);
    V8 a1 = ldg256(rowA + 1024 + 32 * lane);
    V8 b0 = ldg256(rowB + 32 * lane);
    V8 b1 = ldg256(rowB + 1024 + 32 * lane);

    float sa = v8_sum2(a0, a1);
    float sb = v8_sum2(b0, b1);

    // Two independent shuffle chains — interleave in issue slots.
#pragma unroll
    for (int off = 16; off > 0; off >>= 1) {
        sa += __shfl_xor_sync(0xffffffffu, sa, off);
        sb += __shfl_xor_sync(0xffffffffu, sb, off);
    }

    v8_sub(a0, sa); v8_sub(a1, sa);
    v8_sub(b0, sb); v8_sub(b1, sb);

    stg256(orowA + 32 * lane, a0);
    stg256(orowA + 1024 + 32 * lane, a1);
    stg256(orowB + 32 * lane, b0);
    stg256(orowB + 1024 + 32 * lane, b1);
}

extern "C" void kernel_launch(void* const* d_in, const int* in_sizes, int n_in,
                              void* d_out, int out_size) {
    const float* x = (const float*)d_in[0];
    float* out = (float*)d_out;
    const int n_rows = in_sizes[0] / D;   // 65536
    const int n_pairs = n_rows / 2;       // 32768

    const int threads = 256;  // 8 warps/block
    const int warps_per_block = threads / 32;
    const int blocks = (n_pairs + warps_per_block - 1) / warps_per_block;

    row_center_kernel<<<blocks, threads>>>(x, out, n_pairs);
}

// round 9
// speedup vs baseline: 1.0368x; 1.0368x over previous
#include <cuda_runtime.h>

// out[b, s, d] = x[b, s, d] - sum_d' x[b, s, d']
// x: (8, 8192, 512) fp32 -> 65536 rows of 512 floats. Compulsory traffic =
// 268.4 MB; HBM-spec floor = 33.5us. Best kernel = 35.4us (94.6% of floor):
// this op is DRAM-compulsory-traffic bound, all L2/MLP levers were neutral.
// R8: final micro-tune — warp-per-row float4 + streaming hints (best-measured
// combo, R2) with 16-warp CTAs (exact 4096-block grid, no tail guard).

static constexpr int D = 512;
static constexpr int VEC_PER_ROW = D / 4;              // 128 float4 per row
static constexpr int VEC_PER_LANE = VEC_PER_ROW / 32;  // 4

__global__ void __launch_bounds__(512)
row_center_kernel(const float4* __restrict__ x, float4* __restrict__ out) {
    const int warp_global = (blockIdx.x * blockDim.x + threadIdx.x) >> 5;
    const int lane = threadIdx.x & 31;

    const float4* __restrict__ row = x + (size_t)warp_global * VEC_PER_ROW;
    float4* __restrict__ orow = out + (size_t)warp_global * VEC_PER_ROW;

    float4 v[VEC_PER_LANE];
    float s = 0.0f;
#pragma unroll
    for (int i = 0; i < VEC_PER_LANE; i++) {
        v[i] = __ldcs(&row[lane + 32 * i]);
        s += (v[i].x + v[i].y) + (v[i].z + v[i].w);
    }

    // warp tree reduction
#pragma unroll
    for (int off = 16; off > 0; off >>= 1)
        s += __shfl_xor_sync(0xffffffffu, s, off);

#pragma unroll
    for (int i = 0; i < VEC_PER_LANE; i++) {
        float4 r = v[i];
        r.x -= s; r.y -= s; r.z -= s; r.w -= s;
        __stcs(&orow[lane + 32 * i], r);
    }
}

extern "C" void kernel_launch(void* const* d_in, const int* in_sizes, int n_in,
                              void* d_out, int out_size) {
    const float* x = (const float*)d_in[0];
    float* out = (float*)d_out;
    const int n_rows = in_sizes[0] / D;       // 65536
    const int threads = 512;                  // 16 warps/block
    const int blocks = n_rows / (threads / 32);  // 4096, exact

    row_center_kernel<<<blocks, threads>>>(
        (const float4*)x, (float4*)out);
}